// round 1
// baseline (speedup 1.0000x reference)
#include <cuda_runtime.h>
#include <cstdint>

// Scatter-mean message passing:
//   out[t] = mean over edges e with tgt[e]==t of x[src[e]]
// x: [N, 64] f32, edge_idx: [2, E] i32 (row 0 = src, row 1 = tgt)

#define F 64
#define F4 16            // 64 floats = 16 float4
#define MAX_N (1 << 20)

__device__ int g_counts[MAX_N];

__global__ void zero_kernel(float* __restrict__ out, int n_out, int n_counts) {
    int i = blockIdx.x * blockDim.x + threadIdx.x;
    if (i < n_out) out[i] = 0.0f;
    if (i < n_counts) g_counts[i] = 0;
}

__global__ void scatter_kernel(const float4* __restrict__ x,
                               const int* __restrict__ src,
                               const int* __restrict__ tgt,
                               float4* __restrict__ out,
                               int E) {
    int t = blockIdx.x * blockDim.x + threadIdx.x;
    int e = t >> 4;          // edge index
    int c = t & 15;          // float4 chunk within the 64-float row
    if (e >= E) return;

    int s = __ldg(&src[e]);
    int d = __ldg(&tgt[e]);

    float4 v = __ldg(&x[(size_t)s * F4 + c]);

    float4* addr = out + (size_t)d * F4 + c;
    asm volatile("red.global.add.v4.f32 [%0], {%1, %2, %3, %4};"
                 :: "l"(addr), "f"(v.x), "f"(v.y), "f"(v.z), "f"(v.w)
                 : "memory");

    if (c == 0) atomicAdd(&g_counts[d], 1);
}

__global__ void divide_kernel(float4* __restrict__ out, int N) {
    int i = blockIdx.x * blockDim.x + threadIdx.x;
    if (i >= N * F4) return;
    int node = i >> 4;
    int cnt = g_counts[node];
    float inv = 1.0f / (float)(cnt > 0 ? cnt : 1);
    float4 v = out[i];
    v.x *= inv; v.y *= inv; v.z *= inv; v.w *= inv;
    out[i] = v;
}

extern "C" void kernel_launch(void* const* d_in, const int* in_sizes, int n_in,
                              void* d_out, int out_size) {
    const float* x = (const float*)d_in[0];
    const int* edge_idx = (const int*)d_in[1];

    int E = in_sizes[1] / 2;
    int N = out_size / F;           // out is [N, 64]

    const int* src = edge_idx;      // row 0
    const int* tgt = edge_idx + E;  // row 1

    float* out = (float*)d_out;

    // 1) zero output + counts
    {
        int n = out_size > N ? out_size : N;
        int threads = 256;
        int blocks = (n + threads - 1) / threads;
        zero_kernel<<<blocks, threads>>>(out, out_size, N);
    }

    // 2) atomic scatter: 16 threads per edge (one float4 each)
    {
        long long total = (long long)E * F4;
        int threads = 256;
        long long blocks = (total + threads - 1) / threads;
        scatter_kernel<<<(int)blocks, threads>>>((const float4*)x, src, tgt,
                                                 (float4*)d_out, E);
    }

    // 3) divide by counts
    {
        int total = N * F4;
        int threads = 256;
        int blocks = (total + threads - 1) / threads;
        divide_kernel<<<blocks, threads>>>((float4*)d_out, N);
    }
}

// round 2
// speedup vs baseline: 1.4293x; 1.4293x over previous
#include <cuda_runtime.h>
#include <cstdint>
#include <cstddef>

// Scatter-mean message passing via on-the-fly CSR build + per-node gather-reduce.
//   out[t] = mean over edges e with tgt[e]==t of x[src[e]]
// x: [N, 64] f32, edge_idx: [2, E] i32 (row 0 = src, row 1 = tgt)

#define F 64
#define MAX_N (1 << 20)   // >= 100000
#define MAX_E (1 << 21)   // >= 1600000

__device__ int g_hist[MAX_N];     // per-node degree
__device__ int g_off[MAX_N];      // fill cursor; after fill pass holds END of node range
__device__ int g_sorted[MAX_E];   // src indices grouped by target node
__device__ int g_cursor[1];       // global allocation cursor

// 1) degree histogram
__global__ void hist_kernel(const int* __restrict__ tgt, int E) {
    int e = blockIdx.x * blockDim.x + threadIdx.x;
    if (e < E) atomicAdd(&g_hist[tgt[e]], 1);
}

// 2) assign each node a disjoint range [off, off+deg) via global cursor.
//    Placement order is irrelevant for correctness.
__global__ void offsets_kernel(int N) {
    int n = blockIdx.x * blockDim.x + threadIdx.x;
    if (n < N) {
        int deg = g_hist[n];
        g_off[n] = atomicAdd(g_cursor, deg);
    }
}

// 3) fill: place each edge's src into its target's range (g_off becomes range END)
__global__ void fill_kernel(const int* __restrict__ src,
                            const int* __restrict__ tgt, int E) {
    int e = blockIdx.x * blockDim.x + threadIdx.x;
    if (e < E) {
        int d = tgt[e];
        int pos = atomicAdd(&g_off[d], 1);
        g_sorted[pos] = src[e];
    }
}

// 4) aggregate: one warp per node. Each lane owns 2 floats (32 lanes x float2 = 256B row).
//    Registers accumulate the sum; single write of the mean.
__global__ void aggregate_kernel(const float2* __restrict__ x2,
                                 float2* __restrict__ out2, int N) {
    int n = (blockIdx.x * blockDim.x + threadIdx.x) >> 5;
    int lane = threadIdx.x & 31;
    if (n >= N) return;

    int deg = g_hist[n];
    int end = g_off[n];          // after fill pass: start + deg
    int k = end - deg;

    float2 acc0 = make_float2(0.f, 0.f);
    float2 acc1 = make_float2(0.f, 0.f);

    for (; k + 1 < end; k += 2) {
        int s0 = __ldg(&g_sorted[k]);
        int s1 = __ldg(&g_sorted[k + 1]);
        float2 v0 = __ldg(&x2[(size_t)s0 * 32 + lane]);
        float2 v1 = __ldg(&x2[(size_t)s1 * 32 + lane]);
        acc0.x += v0.x; acc0.y += v0.y;
        acc1.x += v1.x; acc1.y += v1.y;
    }
    if (k < end) {
        int s = __ldg(&g_sorted[k]);
        float2 v = __ldg(&x2[(size_t)s * 32 + lane]);
        acc0.x += v.x; acc0.y += v.y;
    }

    float inv = deg > 0 ? 1.0f / (float)deg : 0.0f;
    float2 o;
    o.x = (acc0.x + acc1.x) * inv;
    o.y = (acc0.y + acc1.y) * inv;
    out2[(size_t)n * 32 + lane] = o;   // deg==0 -> writes 0, matching reference
}

extern "C" void kernel_launch(void* const* d_in, const int* in_sizes, int n_in,
                              void* d_out, int out_size) {
    const float* x = (const float*)d_in[0];
    const int* edge_idx = (const int*)d_in[1];

    int E = in_sizes[1] / 2;
    int N = out_size / F;

    const int* src = edge_idx;       // row 0
    const int* tgt = edge_idx + E;   // row 1

    // Zero scratch (hist + cursor) via memset nodes — no zero kernel needed.
    void* hist_ptr = nullptr;
    void* cursor_ptr = nullptr;
    cudaGetSymbolAddress(&hist_ptr, g_hist);
    cudaGetSymbolAddress(&cursor_ptr, g_cursor);
    cudaMemsetAsync(hist_ptr, 0, (size_t)N * sizeof(int));
    cudaMemsetAsync(cursor_ptr, 0, sizeof(int));

    const int T = 256;

    hist_kernel<<<(E + T - 1) / T, T>>>(tgt, E);
    offsets_kernel<<<(N + T - 1) / T, T>>>(N);
    fill_kernel<<<(E + T - 1) / T, T>>>(src, tgt, E);

    // one warp per node -> N*32 threads
    long long total = (long long)N * 32;
    aggregate_kernel<<<(int)((total + T - 1) / T), T>>>(
        (const float2*)x, (float2*)d_out, N);
}

// round 3
// speedup vs baseline: 1.5974x; 1.1176x over previous
#include <cuda_runtime.h>
#include <cstdint>
#include <cstddef>

// Scatter-mean message passing via single-pass padded-CSR build + per-node gather-reduce.
//   out[t] = mean over edges e with tgt[e]==t of x[src[e]]
// x: [N, 64] f32, edge_idx: [2, E] i32 (row 0 = src, row 1 = tgt)

#define F 64
#define MAX_N (1 << 17)      // >= 100000
#define SLOTS 64             // padded CSR row capacity (Poisson(16): P(deg>64) ~ 1e-20)
#define MAX_OVER 8192        // overflow spill capacity (correctness fallback)

__device__ int g_cnt[MAX_N];                  // per-node edge count (true degree)
__device__ int g_sorted[(size_t)MAX_N * SLOTS];  // padded per-node src lists
__device__ int g_over_src[MAX_OVER];
__device__ int g_over_tgt[MAX_OVER];
__device__ int g_over_cnt[1];

__device__ __forceinline__ void place_edge(int s, int d) {
    int pos = atomicAdd(&g_cnt[d], 1);
    if (pos < SLOTS) {
        g_sorted[(size_t)d * SLOTS + pos] = s;
    } else {
        int op = atomicAdd(&g_over_cnt[0], 1);
        if (op < MAX_OVER) { g_over_src[op] = s; g_over_tgt[op] = d; }
    }
}

// Single build pass: 4 edges per thread via int4.
__global__ void fill_kernel(const int4* __restrict__ src4,
                            const int4* __restrict__ tgt4, int E4,
                            const int* __restrict__ src,
                            const int* __restrict__ tgt, int E) {
    int t = blockIdx.x * blockDim.x + threadIdx.x;
    if (t < E4) {
        int4 s = __ldg(&src4[t]);
        int4 d = __ldg(&tgt4[t]);
        place_edge(s.x, d.x);
        place_edge(s.y, d.y);
        place_edge(s.z, d.z);
        place_edge(s.w, d.w);
    }
    if (t == 0) {
        for (int e = E4 * 4; e < E; e++) place_edge(src[e], tgt[e]);
    }
}

__device__ __forceinline__ unsigned long long f2add(unsigned long long a,
                                                    unsigned long long b) {
    unsigned long long r;
    asm("add.rn.f32x2 %0, %1, %2;" : "=l"(r) : "l"(a), "l"(b));
    return r;
}

// One warp per node. Lane owns 8 bytes (float2) of the 256B row.
// 32 indices fetched per coalesced LDG, broadcast via shfl; 4-deep gather MLP;
// packed f32x2 accumulation.
__global__ void aggregate_kernel(const char* __restrict__ xbase,
                                 float2* __restrict__ out2, int N) {
    int n = (blockIdx.x * blockDim.x + threadIdx.x) >> 5;
    int lane = threadIdx.x & 31;
    if (n >= N) return;

    int count = g_cnt[n];
    int m = count < SLOTS ? count : SLOTS;
    const char* xlane = xbase + (lane << 3);
    const int* row = &g_sorted[(size_t)n * SLOTS];

    unsigned long long a0 = 0ull, a1 = 0ull, a2 = 0ull, a3 = 0ull;

    for (int base = 0; base < m; base += 32) {
        int rem = m - base;
        if (rem > 32) rem = 32;
        int idx = 0;
        if (lane < rem) idx = __ldg(&row[base + lane]);

        int j = 0;
        for (; j + 3 < rem; j += 4) {
            int s0 = __shfl_sync(0xffffffffu, idx, j);
            int s1 = __shfl_sync(0xffffffffu, idx, j + 1);
            int s2 = __shfl_sync(0xffffffffu, idx, j + 2);
            int s3 = __shfl_sync(0xffffffffu, idx, j + 3);
            unsigned long long v0 = __ldg((const unsigned long long*)(xlane + ((size_t)s0 << 8)));
            unsigned long long v1 = __ldg((const unsigned long long*)(xlane + ((size_t)s1 << 8)));
            unsigned long long v2 = __ldg((const unsigned long long*)(xlane + ((size_t)s2 << 8)));
            unsigned long long v3 = __ldg((const unsigned long long*)(xlane + ((size_t)s3 << 8)));
            a0 = f2add(a0, v0);
            a1 = f2add(a1, v1);
            a2 = f2add(a2, v2);
            a3 = f2add(a3, v3);
        }
        for (; j < rem; j++) {
            int s = __shfl_sync(0xffffffffu, idx, j);
            unsigned long long v = __ldg((const unsigned long long*)(xlane + ((size_t)s << 8)));
            a0 = f2add(a0, v);
        }
    }

    // Overflow fallback (cold: only if some node's degree exceeded SLOTS).
    if (count > SLOTS) {
        int oc = g_over_cnt[0];
        for (int i = 0; i < oc; i++) {
            if (g_over_tgt[i] == n) {
                int s = g_over_src[i];
                unsigned long long v = __ldg((const unsigned long long*)(xlane + ((size_t)s << 8)));
                a0 = f2add(a0, v);
            }
        }
    }

    a0 = f2add(a0, a1);
    a2 = f2add(a2, a3);
    a0 = f2add(a0, a2);

    unsigned int lo, hi;
    asm("mov.b64 {%0, %1}, %2;" : "=r"(lo), "=r"(hi) : "l"(a0));

    float inv = count > 0 ? 1.0f / (float)count : 0.0f;
    float2 o;
    o.x = __uint_as_float(lo) * inv;
    o.y = __uint_as_float(hi) * inv;
    out2[(size_t)n * 32 + lane] = o;
}

extern "C" void kernel_launch(void* const* d_in, const int* in_sizes, int n_in,
                              void* d_out, int out_size) {
    const float* x = (const float*)d_in[0];
    const int* edge_idx = (const int*)d_in[1];

    int E = in_sizes[1] / 2;
    int N = out_size / F;

    const int* src = edge_idx;       // row 0
    const int* tgt = edge_idx + E;   // row 1

    // Zero scratch counters via memset nodes.
    void* cnt_ptr = nullptr;
    void* over_ptr = nullptr;
    cudaGetSymbolAddress(&cnt_ptr, g_cnt);
    cudaGetSymbolAddress(&over_ptr, g_over_cnt);
    cudaMemsetAsync(cnt_ptr, 0, (size_t)N * sizeof(int));
    cudaMemsetAsync(over_ptr, 0, sizeof(int));

    const int T = 256;

    int E4 = E / 4;
    int fill_blocks = (E4 + T - 1) / T;
    if (fill_blocks < 1) fill_blocks = 1;
    fill_kernel<<<fill_blocks, T>>>((const int4*)src, (const int4*)tgt, E4,
                                    src, tgt, E);

    long long total = (long long)N * 32;
    aggregate_kernel<<<(int)((total + T - 1) / T), T>>>(
        (const char*)x, (float2*)d_out, N);
}